// round 1
// baseline (speedup 1.0000x reference)
#include <cuda_runtime.h>
#include <cstdint>

#define NN 2048
#define BS 256
#define THRESH 0.3f
#define OVERLAP 0.5f

__global__ __launch_bounds__(BS) void det_kernel(
    const float* __restrict__ loc,    // (8,2048,2)
    const float* __restrict__ cls,    // (8,2048,5)
    const float* __restrict__ dflt,   // (2048,2)
    float* __restrict__ out)          // (8,4,2048,3)
{
    __shared__ float s_start[NN];
    __shared__ float s_end[NN];
    __shared__ float s_score[NN];
    __shared__ unsigned long long s_key[NN];
    __shared__ unsigned char s_keep[NN];
    __shared__ unsigned char s_keep_orig[NN];
    __shared__ int s_m;

    const int b = blockIdx.x >> 2;
    const int c = blockIdx.x & 3;      // class index into scores[1..4]
    const int tid = threadIdx.x;

    if (tid == 0) s_m = 0;
    __syncthreads();

    const float* locb = loc + (size_t)b * NN * 2;
    const float* clsb = cls + (size_t)b * NN * 5;

    // ---- decode boxes + softmax score for this class + sort keys ----
    int local_cnt = 0;
    for (int n = tid; n < NN; n += BS) {
        float dc = dflt[n * 2 + 0];
        float dw = dflt[n * 2 + 1];
        float l0 = locb[n * 2 + 0];
        float l1 = locb[n * 2 + 1];
        float ctr = dc + l0 * dw;
        float w   = dw * expf(l1);
        float st  = ctr - 0.5f * w;
        float en  = ctr + 0.5f * w;
        s_start[n] = st;
        s_end[n]   = en;

        float x0 = clsb[n * 5 + 0];
        float x1 = clsb[n * 5 + 1];
        float x2 = clsb[n * 5 + 2];
        float x3 = clsb[n * 5 + 3];
        float x4 = clsb[n * 5 + 4];
        float mx = fmaxf(fmaxf(fmaxf(x0, x1), fmaxf(x2, x3)), x4);
        float sum = expf(x0 - mx) + expf(x1 - mx) + expf(x2 - mx)
                  + expf(x3 - mx) + expf(x4 - mx);
        float xc = clsb[n * 5 + 1 + c];
        float sc = expf(xc - mx) / sum;
        s_score[n] = sc;

        unsigned long long key = 0ull;
        if (sc > THRESH) {
            unsigned int sb = __float_as_uint(sc);  // positive floats: bit-monotone
            key = ((unsigned long long)sb << 32) | (unsigned int)(2047 - n);
            local_cnt++;
        }
        s_key[n] = key;
    }
    if (local_cnt) atomicAdd(&s_m, local_cnt);
    __syncthreads();
    const int M = s_m;

    // ---- bitonic sort descending over 2048 u64 keys ----
    // Descending sort on (score_bits, 2047-n) == JAX stable argsort(-masked):
    // higher score first; equal score -> smaller n first. Invalid (key==0) last.
    for (int k = 2; k <= NN; k <<= 1) {
        for (int j = k >> 1; j > 0; j >>= 1) {
            __syncthreads();
            #pragma unroll 4
            for (int t = tid; t < NN / 2; t += BS) {
                int i = ((t & ~(j - 1)) << 1) | (t & (j - 1));
                int l = i | j;
                unsigned long long a  = s_key[i];
                unsigned long long bb = s_key[l];
                bool desc = ((i & k) == 0);
                if ((a < bb) == desc) { s_key[i] = bb; s_key[l] = a; }
            }
        }
    }
    __syncthreads();

    // ---- greedy NMS over the M valid items (sorted) ----
    for (int j = tid; j < M; j += BS) s_keep[j] = 1;
    __syncthreads();

    for (int i = 0; i < M; i++) {
        // s_keep[i] is uniform across the block here (post-sync) -> uniform branch
        if (s_keep[i]) {
            int  ni = 2047 - (int)(unsigned int)s_key[i];
            float si = s_start[ni];
            float ei = s_end[ni];
            float li = ei - si;
            for (int j = i + 1 + tid; j < M; j += BS) {
                if (!s_keep[j]) continue;
                int  nj = 2047 - (int)(unsigned int)s_key[j];
                float sj = s_start[nj];
                float ej = s_end[nj];
                float inter = fminf(ei, ej) - fmaxf(si, sj);
                inter = fmaxf(inter, 0.0f);
                float uni = li + (ej - sj) - inter;
                float iou = inter / fmaxf(uni, 1e-12f);
                if (iou > OVERLAP) s_keep[j] = 0;
            }
        }
        __syncthreads();
    }

    // ---- scatter keep back to original order ----
    for (int n = tid; n < NN; n += BS) s_keep_orig[n] = 0;
    __syncthreads();
    for (int j = tid; j < M; j += BS) {
        if (s_keep[j]) {
            int n = 2047 - (int)(unsigned int)s_key[j];
            s_keep_orig[n] = 1;
        }
    }
    __syncthreads();

    // ---- write output slice (in_range applied AFTER NMS, as in reference) ----
    float* ob = out + (size_t)(b * 4 + c) * NN * 3;
    for (int n = tid; n < NN; n += BS) {
        float st = s_start[n];
        float en = s_end[n];
        bool kp = s_keep_orig[n] && (st > -10.0f) && (en < 10.0f);
        ob[n * 3 + 0] = kp ? st : 0.0f;
        ob[n * 3 + 1] = kp ? en : 0.0f;
        ob[n * 3 + 2] = kp ? s_score[n] : 0.0f;
    }
}

extern "C" void kernel_launch(void* const* d_in, const int* in_sizes, int n_in,
                              void* d_out, int out_size) {
    const float* loc  = (const float*)d_in[0];  // (8,2048,2)
    const float* cls  = (const float*)d_in[1];  // (8,2048,5)
    const float* dflt = (const float*)d_in[2];  // (2048,2)
    float* out = (float*)d_out;                 // (8,4,2048,3)
    det_kernel<<<32, BS>>>(loc, cls, dflt, out);
}